// round 1
// baseline (speedup 1.0000x reference)
#include <cuda_runtime.h>
#include <cstdint>

// Problem shape (fixed by the bench's setup_inputs):
//   q  [B,Sq,D]      (unused — dead code after softmax-over-heads collapse)
//   k  [Sk,B,D]      (unused)
//   v  [B,Sq,D]
//   Wv [dh,D], bv [dh], Wb [D,dh], bb [D]
//   out [Sk,B,D]
// Math after collapse:
//   attn == 1/H exactly (softmax over an exactly-broadcast head axis)
//   row[b,d] = (1/H) * sum_j ( (sum_q v[b,q,:]) . Wv[j,:] + Sq*bv[j] ) * Wb[d,j] + bb[d]
//   out[s,b,d] = row[b,d]  for all s
static constexpr int B  = 4;
static constexpr int SQ = 1024;
static constexpr int SK = 1024;
static constexpr int D  = 1024;
static constexpr int DH = 64;
static constexpr int H  = 16;

static constexpr int QS    = 64;        // q-splits for the v reduction
static constexpr int QROWS = SQ / QS;   // 16 rows per split

// Scratch (no allocations allowed in kernel_launch)
__device__ float g_partial[QS * B * D];  // 1 MB: partial column sums of v
__device__ float g_row[B * D];           // 16 KB: final per-(b,d) row

// ---------------------------------------------------------------------------
// Kernel A: partial column-sum of v over the Sq axis.
// grid (B, QS) x 256 threads; each thread owns one float4 of D, sums QROWS rows.
// Fully coalesced: at fixed q, consecutive threads read consecutive d.
// ---------------------------------------------------------------------------
__global__ void __launch_bounds__(256) reduce_v_kernel(const float* __restrict__ v) {
    const int b  = blockIdx.x;
    const int qs = blockIdx.y;
    const int t  = threadIdx.x;                 // float4 index into D/4=256
    const float4* vb = reinterpret_cast<const float4*>(v + (size_t)b * SQ * D);
    const int q0 = qs * QROWS;

    float4 acc = make_float4(0.f, 0.f, 0.f, 0.f);
#pragma unroll
    for (int r = 0; r < QROWS; ++r) {
        float4 x = vb[(size_t)(q0 + r) * (D / 4) + t];
        acc.x += x.x; acc.y += x.y; acc.z += x.z; acc.w += x.w;
    }
    reinterpret_cast<float4*>(g_partial)[(size_t)(qs * B + b) * (D / 4) + t] = acc;
}

// ---------------------------------------------------------------------------
// Kernel B: finish the reduction + both tiny GEMVs. grid = B blocks, 256 thr.
//   stage 1: vsum[b,:]  = sum over QS partials           (shared, 4 KB)
//   stage 2: sv[j]      = vsum . Wv[j,:] + Sq*bv[j]      (warp-per-j dot)
//   stage 3: row[b,d]   = (1/H) * sv . Wb[d,:] + bb[d]
// ---------------------------------------------------------------------------
__global__ void __launch_bounds__(256) combine_kernel(const float* __restrict__ Wv,
                                                      const float* __restrict__ bv,
                                                      const float* __restrict__ Wb,
                                                      const float* __restrict__ bb) {
    __shared__ float s_vsum[D];   // 4 KB
    __shared__ float s_sv[DH];    // 256 B

    const int b = blockIdx.x;
    const int t = threadIdx.x;

    // stage 1: reduce the QS partials for this batch
    float4 acc = make_float4(0.f, 0.f, 0.f, 0.f);
#pragma unroll 8
    for (int qs = 0; qs < QS; ++qs) {
        float4 x = reinterpret_cast<const float4*>(g_partial)[(size_t)(qs * B + b) * (D / 4) + t];
        acc.x += x.x; acc.y += x.y; acc.z += x.z; acc.w += x.w;
    }
    reinterpret_cast<float4*>(s_vsum)[t] = acc;
    __syncthreads();

    // stage 2: sv[j] = <vsum, Wv[j,:]> + Sq*bv[j]   (one warp per j, 8 j's/warp)
    const int warp = t >> 5, lane = t & 31;
    for (int j = warp; j < DH; j += 8) {
        const float* wrow = Wv + (size_t)j * D;
        float s = 0.f;
        for (int i = lane; i < D; i += 32) s += s_vsum[i] * wrow[i];
#pragma unroll
        for (int o = 16; o > 0; o >>= 1) s += __shfl_xor_sync(0xFFFFFFFFu, s, o);
        if (lane == 0) s_sv[j] = s + (float)SQ * bv[j];
    }
    __syncthreads();

    // stage 3: row[b,d] = (1/H)*<sv, Wb[d,:]> + bb[d]   (4 d's per thread)
#pragma unroll
    for (int dd = 0; dd < 4; ++dd) {
        const int d = t + dd * 256;
        const float4* wb = reinterpret_cast<const float4*>(Wb + (size_t)d * DH);
        float s = 0.f;
#pragma unroll
        for (int j4 = 0; j4 < DH / 4; ++j4) {
            float4 w = wb[j4];
            s += s_sv[j4 * 4 + 0] * w.x + s_sv[j4 * 4 + 1] * w.y
               + s_sv[j4 * 4 + 2] * w.z + s_sv[j4 * 4 + 3] * w.w;
        }
        g_row[b * D + d] = s * (1.0f / (float)H) + bb[d];
    }
}

// ---------------------------------------------------------------------------
// Kernel C: broadcast-write. out[s,b,d] = row[b,d]; flattened, out is the
// 4096-float row tile repeated SK times. Pure streaming write (16 MB).
// ---------------------------------------------------------------------------
__global__ void __launch_bounds__(256) bcast_kernel(float4* __restrict__ out) {
    const int i = blockIdx.x * blockDim.x + threadIdx.x;   // 0 .. SK*B*D/4-1
    const float4 val = __ldg(&reinterpret_cast<const float4*>(g_row)[i & (B * D / 4 - 1)]);
    out[i] = val;
}

extern "C" void kernel_launch(void* const* d_in, const int* in_sizes, int n_in,
                              void* d_out, int out_size) {
    // Input order (metadata): 0=q 1=k 2=h 3=w 4=v 5=Wq 6=bq 7=Wk 8=bk 9=Wv 10=bv 11=Wb 12=bb
    const float* v  = (const float*)d_in[4];
    const float* Wv = (const float*)d_in[9];
    const float* bv = (const float*)d_in[10];
    const float* Wb = (const float*)d_in[11];
    const float* bb = (const float*)d_in[12];
    float* out = (float*)d_out;

    reduce_v_kernel<<<dim3(B, QS), 256>>>(v);
    combine_kernel<<<B, 256>>>(Wv, bv, Wb, bb);
    const int n4 = SK * B * D / 4;            // 1,048,576 float4 stores
    bcast_kernel<<<n4 / 256, 256>>>((float4*)out);
}

// round 2
// speedup vs baseline: 1.5635x; 1.5635x over previous
#include <cuda_runtime.h>
#include <cstdint>

// Math after collapse (verified round 1, rel_err 9e-7):
//   attn == 1/H exactly (softmax over an exactly-broadcast head axis)
//   sv[b,j]  = <sum_q v[b,q,:], Wv[j,:]> + Sq*bv[j]
//   row[b,d] = (1/H) * <sv[b,:], Wb[d,:]> + bb[d]
//   out[s,b,d] = row[b,d]  for all s
static constexpr int B  = 4;
static constexpr int SQ = 1024;
static constexpr int SK = 1024;
static constexpr int D  = 1024;
static constexpr int DH = 64;
static constexpr int H  = 16;

static constexpr int QS = 64;            // q-splits (blocks.y in kernel A)
// Each A block: 1024 threads = 4 strips x 256 d-slots, each strip sums 4 rows
// -> block covers 16 q-rows, QS*16 = 1024 = SQ.

// Scratch (__device__ globals; no allocation allowed)
__device__ float g_partial[QS * B * D];      // 1 MB: per-(qs,b) partial row sums
__device__ float g_svp[4 * B * DH];          // 4 KB: per-d-chunk partial sv
__device__ float g_row[B * D];               // 16 KB: final per-(b,d) row

// ---------------------------------------------------------------------------
// A: column-sum v over Sq. grid (B, QS) x 1024 threads.
// 4 strips of 256 threads; strip s sums rows [qs*16 + 4s, +4); smem combine.
// ---------------------------------------------------------------------------
__global__ void __launch_bounds__(1024) reduce_v_kernel(const float* __restrict__ v) {
    const int b     = blockIdx.x;
    const int qs    = blockIdx.y;
    const int t     = threadIdx.x;
    const int t4    = t & 255;          // d-slot (float4)
    const int strip = t >> 8;           // 0..3

    const float4* vb = reinterpret_cast<const float4*>(v + (size_t)b * SQ * D);
    const int q0 = qs * 16 + strip * 4;

    float4 acc = make_float4(0.f, 0.f, 0.f, 0.f);
#pragma unroll
    for (int r = 0; r < 4; ++r) {
        float4 x = vb[(size_t)(q0 + r) * (D / 4) + t4];
        acc.x += x.x; acc.y += x.y; acc.z += x.z; acc.w += x.w;
    }

    __shared__ float4 sred[4][256];     // 16 KB
    sred[strip][t4] = acc;
    __syncthreads();

    if (strip == 0) {
        float4 a0 = sred[0][t4], a1 = sred[1][t4], a2 = sred[2][t4], a3 = sred[3][t4];
        float4 s;
        s.x = (a0.x + a1.x) + (a2.x + a3.x);
        s.y = (a0.y + a1.y) + (a2.y + a3.y);
        s.z = (a0.z + a1.z) + (a2.z + a3.z);
        s.w = (a0.w + a1.w) + (a2.w + a3.w);
        reinterpret_cast<float4*>(g_partial)[(size_t)(qs * B + b) * (D / 4) + t4] = s;
    }
}

// ---------------------------------------------------------------------------
// B1: finish vsum per 256-float d-chunk, then project through Wv.
// grid (B, 4) x 256 threads. Block (b,c) owns d-chunk [c*256, c*256+256).
//   stage 1: vsum_chunk = sum over QS partials (4-way qs split + smem reduce)
//   stage 2: g_svp[c][b][j] = <vsum_chunk, Wv[j, chunk]>  (warp-per-8j dots)
// Deterministic: fixed-order adds everywhere.
// ---------------------------------------------------------------------------
__global__ void __launch_bounds__(256) gemv1_kernel(const float* __restrict__ Wv) {
    const int b = blockIdx.x;
    const int c = blockIdx.y;           // d-chunk index, 0..3
    const int t = threadIdx.x;

    const int slot = t & 63;            // float4 slot within chunk (64 slots)
    const int qsub = t >> 6;            // 0..3: split over qs

    float4 acc = make_float4(0.f, 0.f, 0.f, 0.f);
#pragma unroll 4
    for (int q = qsub; q < QS; q += 4) {
        float4 x = reinterpret_cast<const float4*>(g_partial)
                       [(size_t)(q * B + b) * (D / 4) + c * 64 + slot];
        acc.x += x.x; acc.y += x.y; acc.z += x.z; acc.w += x.w;
    }

    __shared__ float4 sred[256];
    __shared__ float  s_v[256];         // vsum for this chunk
    sred[t] = acc;
    __syncthreads();
    if (qsub == 0) {
        float4 a0 = sred[slot], a1 = sred[64 + slot], a2 = sred[128 + slot], a3 = sred[192 + slot];
        float4 s;
        s.x = (a0.x + a1.x) + (a2.x + a3.x);
        s.y = (a0.y + a1.y) + (a2.y + a3.y);
        s.z = (a0.z + a1.z) + (a2.z + a3.z);
        s.w = (a0.w + a1.w) + (a2.w + a3.w);
        reinterpret_cast<float4*>(s_v)[slot] = s;
    }
    __syncthreads();

    // stage 2: 8 warps x 8 j's each
    const int warp = t >> 5, lane = t & 31;
#pragma unroll
    for (int jj = 0; jj < 8; ++jj) {
        const int j = warp * 8 + jj;
        const float* wr = Wv + (size_t)j * D + c * 256;
        float s = 0.f;
#pragma unroll
        for (int i = 0; i < 8; ++i) s += s_v[lane + i * 32] * wr[lane + i * 32];
#pragma unroll
        for (int o = 16; o > 0; o >>= 1) s += __shfl_xor_sync(0xFFFFFFFFu, s, o);
        if (lane == 0) g_svp[(c * B + b) * DH + j] = s;
    }
}

// ---------------------------------------------------------------------------
// B2: sv = sum of 4 chunk-partials + Sq*bv; row = (1/H)*sv.Wb^T + bb.
// grid (B, 4) x 256 threads; block (b,c) writes row d-chunk [c*256, +256).
// ---------------------------------------------------------------------------
__global__ void __launch_bounds__(256) gemv2_kernel(const float* __restrict__ bv,
                                                    const float* __restrict__ Wb,
                                                    const float* __restrict__ bb) {
    const int b = blockIdx.x;
    const int c = blockIdx.y;
    const int t = threadIdx.x;

    __shared__ float s_sv[DH];
    if (t < DH) {
        float s = (float)SQ * bv[t];
        s += ((g_svp[(0 * B + b) * DH + t] + g_svp[(1 * B + b) * DH + t])
            + (g_svp[(2 * B + b) * DH + t] + g_svp[(3 * B + b) * DH + t]));
        s_sv[t] = s;
    }
    __syncthreads();

    const int d = c * 256 + t;
    const float4* wb = reinterpret_cast<const float4*>(Wb + (size_t)d * DH);
    float s = 0.f;
#pragma unroll
    for (int j4 = 0; j4 < DH / 4; ++j4) {
        float4 w = wb[j4];
        s += s_sv[j4 * 4 + 0] * w.x + s_sv[j4 * 4 + 1] * w.y
           + s_sv[j4 * 4 + 2] * w.z + s_sv[j4 * 4 + 3] * w.w;
    }
    g_row[b * D + d] = s * (1.0f / (float)H) + bb[d];
}

// ---------------------------------------------------------------------------
// C: broadcast-write. out flattened is the 4096-float row tile repeated SK x.
// ---------------------------------------------------------------------------
__global__ void __launch_bounds__(256) bcast_kernel(float4* __restrict__ out) {
    const int i = blockIdx.x * blockDim.x + threadIdx.x;
    const float4 val = __ldg(&reinterpret_cast<const float4*>(g_row)[i & (B * D / 4 - 1)]);
    out[i] = val;
}

extern "C" void kernel_launch(void* const* d_in, const int* in_sizes, int n_in,
                              void* d_out, int out_size) {
    // Inputs: 0=q 1=k 2=h 3=w 4=v 5=Wq 6=bq 7=Wk 8=bk 9=Wv 10=bv 11=Wb 12=bb
    const float* v  = (const float*)d_in[4];
    const float* Wv = (const float*)d_in[9];
    const float* bv = (const float*)d_in[10];
    const float* Wb = (const float*)d_in[11];
    const float* bb = (const float*)d_in[12];
    float* out = (float*)d_out;

    reduce_v_kernel<<<dim3(B, QS), 1024>>>(v);
    gemv1_kernel<<<dim3(B, 4), 256>>>(Wv);
    gemv2_kernel<<<dim3(B, 4), 256>>>(bv, Wb, bb);
    bcast_kernel<<<(SK * B * D / 4) / 256, 256>>>((float4*)out);
}

// round 3
// speedup vs baseline: 1.7524x; 1.1209x over previous
#include <cuda_runtime.h>
#include <cstdint>

// Math after collapse (verified, rel_err ~9e-7):
//   attn == 1/H exactly (softmax over an exactly-broadcast head axis)
//   sv[b,j]  = <sum_q v[b,q,:], Wv[j,:]> + Sq*bv[j]
//   row[b,d] = (1/H) * <sv[b,:], Wb[d,:]> + bb[d]
//   out[s,b,d] = row[b,d]  for all s
static constexpr int B  = 4;
static constexpr int SQ = 1024;
static constexpr int SK = 1024;
static constexpr int D  = 1024;
static constexpr int DH = 64;
static constexpr int H  = 16;

static constexpr int QS = 32;            // q-splits -> B*QS = 128 blocks (single wave)

// Scratch (__device__ globals; no allocation allowed)
__device__ float g_partial[QS * B * D];      // 512 KB: per-(qs,b) partial row sums
__device__ float g_svp[4 * B * DH];          // 4 KB: per-d-chunk partial sv
__device__ float g_row[B * D];               // 16 KB: final per-(b,d) row

// ---------------------------------------------------------------------------
// A: column-sum v over Sq. grid (B, QS)=128 blocks x 1024 threads.
// 4 strips of 256 threads; strip s sums 8 rows [qs*32 + 8s, +8); smem combine.
// Single wave on 148 SMs, 8 LDG.128 in flight per thread.
// ---------------------------------------------------------------------------
__global__ void __launch_bounds__(1024) reduce_v_kernel(const float* __restrict__ v) {
    const int b     = blockIdx.x;
    const int qs    = blockIdx.y;
    const int t     = threadIdx.x;
    const int t4    = t & 255;          // d-slot (float4)
    const int strip = t >> 8;           // 0..3

    const float4* vb = reinterpret_cast<const float4*>(v + (size_t)b * SQ * D);
    const int q0 = qs * 32 + strip * 8;

    float4 acc = make_float4(0.f, 0.f, 0.f, 0.f);
#pragma unroll
    for (int r = 0; r < 8; ++r) {
        float4 x = vb[(size_t)(q0 + r) * (D / 4) + t4];
        acc.x += x.x; acc.y += x.y; acc.z += x.z; acc.w += x.w;
    }

    __shared__ float4 sred[4][256];     // 16 KB
    sred[strip][t4] = acc;
    __syncthreads();

    if (strip == 0) {
        float4 a0 = sred[0][t4], a1 = sred[1][t4], a2 = sred[2][t4], a3 = sred[3][t4];
        float4 s;
        s.x = (a0.x + a1.x) + (a2.x + a3.x);
        s.y = (a0.y + a1.y) + (a2.y + a3.y);
        s.z = (a0.z + a1.z) + (a2.z + a3.z);
        s.w = (a0.w + a1.w) + (a2.w + a3.w);
        reinterpret_cast<float4*>(g_partial)[(size_t)(qs * B + b) * (D / 4) + t4] = s;
    }
}

// ---------------------------------------------------------------------------
// B1: finish vsum per 256-float d-chunk, project through Wv.
// grid (B, 4) x 256 threads. Block (b,c) owns d-chunk [c*256, +256).
// ---------------------------------------------------------------------------
__global__ void __launch_bounds__(256) gemv1_kernel(const float* __restrict__ Wv) {
    const int b = blockIdx.x;
    const int c = blockIdx.y;           // d-chunk index, 0..3
    const int t = threadIdx.x;

    const int slot = t & 63;            // float4 slot within chunk (64 slots)
    const int qsub = t >> 6;            // 0..3: split over qs

    float4 acc = make_float4(0.f, 0.f, 0.f, 0.f);
#pragma unroll
    for (int q = qsub; q < QS; q += 4) {
        float4 x = reinterpret_cast<const float4*>(g_partial)
                       [(size_t)(q * B + b) * (D / 4) + c * 64 + slot];
        acc.x += x.x; acc.y += x.y; acc.z += x.z; acc.w += x.w;
    }

    __shared__ float4 sred[256];
    __shared__ float  s_v[256];         // vsum for this chunk
    sred[t] = acc;
    __syncthreads();
    if (qsub == 0) {
        float4 a0 = sred[slot], a1 = sred[64 + slot], a2 = sred[128 + slot], a3 = sred[192 + slot];
        float4 s;
        s.x = (a0.x + a1.x) + (a2.x + a3.x);
        s.y = (a0.y + a1.y) + (a2.y + a3.y);
        s.z = (a0.z + a1.z) + (a2.z + a3.z);
        s.w = (a0.w + a1.w) + (a2.w + a3.w);
        reinterpret_cast<float4*>(s_v)[slot] = s;
    }
    __syncthreads();

    // 8 warps x 8 j's each
    const int warp = t >> 5, lane = t & 31;
#pragma unroll
    for (int jj = 0; jj < 8; ++jj) {
        const int j = warp * 8 + jj;
        const float* wr = Wv + (size_t)j * D + c * 256;
        float s = 0.f;
#pragma unroll
        for (int i = 0; i < 8; ++i) s += s_v[lane + i * 32] * wr[lane + i * 32];
#pragma unroll
        for (int o = 16; o > 0; o >>= 1) s += __shfl_xor_sync(0xFFFFFFFFu, s, o);
        if (lane == 0) g_svp[(c * B + b) * DH + j] = s;
    }
}

// ---------------------------------------------------------------------------
// B2: sv = sum of 4 chunk-partials + Sq*bv; row = (1/H)*sv.Wb^T + bb.
// grid (B, 4) x 256 threads; block (b,c) writes row d-chunk [c*256, +256).
// ---------------------------------------------------------------------------
__global__ void __launch_bounds__(256) gemv2_kernel(const float* __restrict__ bv,
                                                    const float* __restrict__ Wb,
                                                    const float* __restrict__ bb) {
    const int b = blockIdx.x;
    const int c = blockIdx.y;
    const int t = threadIdx.x;

    __shared__ float s_sv[DH];
    if (t < DH) {
        float s = (float)SQ * bv[t];
        s += ((g_svp[(0 * B + b) * DH + t] + g_svp[(1 * B + b) * DH + t])
            + (g_svp[(2 * B + b) * DH + t] + g_svp[(3 * B + b) * DH + t]));
        s_sv[t] = s;
    }
    __syncthreads();

    const int d = c * 256 + t;
    const float4* wb = reinterpret_cast<const float4*>(Wb + (size_t)d * DH);
    float s = 0.f;
#pragma unroll
    for (int j4 = 0; j4 < DH / 4; ++j4) {
        float4 w = wb[j4];
        s += s_sv[j4 * 4 + 0] * w.x + s_sv[j4 * 4 + 1] * w.y
           + s_sv[j4 * 4 + 2] * w.z + s_sv[j4 * 4 + 3] * w.w;
    }
    g_row[b * D + d] = s * (1.0f / (float)H) + bb[d];
}

// ---------------------------------------------------------------------------
// C: broadcast-write, 8 stores per thread. Thread i loads its row float4 once
// (16 KB tile, L1-resident) and writes out[i + s*STRIDE] for s=0..7.
// STRIDE = 131072 float4 is a multiple of B*D/4 = 1024, so the value is
// invariant across the 8 stores; warp stores stay 512B-contiguous.
// ---------------------------------------------------------------------------
static constexpr int C_THREADS = (SK * B * D / 4) / 8;   // 131072
__global__ void __launch_bounds__(256) bcast_kernel(float4* __restrict__ out) {
    const int i = blockIdx.x * blockDim.x + threadIdx.x;      // 0 .. 131071
    const float4 val = __ldg(&reinterpret_cast<const float4*>(g_row)[i & (B * D / 4 - 1)]);
#pragma unroll
    for (int s = 0; s < 8; ++s)
        out[i + s * C_THREADS] = val;
}

extern "C" void kernel_launch(void* const* d_in, const int* in_sizes, int n_in,
                              void* d_out, int out_size) {
    // Inputs: 0=q 1=k 2=h 3=w 4=v 5=Wq 6=bq 7=Wk 8=bk 9=Wv 10=bv 11=Wb 12=bb
    const float* v  = (const float*)d_in[4];
    const float* Wv = (const float*)d_in[9];
    const float* bv = (const float*)d_in[10];
    const float* Wb = (const float*)d_in[11];
    const float* bb = (const float*)d_in[12];
    float* out = (float*)d_out;

    reduce_v_kernel<<<dim3(B, QS), 1024>>>(v);
    gemv1_kernel<<<dim3(B, 4), 256>>>(Wv);
    gemv2_kernel<<<dim3(B, 4), 256>>>(bv, Wb, bb);
    bcast_kernel<<<C_THREADS / 256, 256>>>((float4*)out);
}